// round 8
// baseline (speedup 1.0000x reference)
#include <cuda_runtime.h>
#include <math.h>

#define NB    16
#define NS    512
#define NBINS 511
#define TILE_V 8
#define NT    (NS / TILE_V)   // 64 column tiles
#define RROWS 4               // rows per block in row_fft

// Transposed row-FFT spectra: [sig][batch][pos][row]. 67 MB.
__device__ float2 g_specT[2][NB][NS][NS];
// Per-(sig, batch, tile) partial shell sums. 4 MB.
__device__ float  g_part[2][NB][NT][512];
// Stage-2 partials for the reduction tree.
__device__ float  g_p2[2][NB][8][512];
// Bin table [pos][k] with bit-reversal baked in. 512 KB.
__device__ unsigned short g_tab[NS * NS];
// Twiddle table, per-stage contiguous: segment for stage `half` starts at
// offset 512 - 2*half and holds W_{2*half}^j, j = 0..half-1.
__device__ float2 g_twk[512];
__device__ double g_bsum[NB];

__device__ __forceinline__ unsigned brev9(unsigned x) { return __brev(x) >> 23; }

// ---------------- setup kernels ----------------

__global__ void twk_kernel() {
    const int i = threadIdx.x;
#pragma unroll
    for (int half = 256; half >= 1; half >>= 1) {
        const int off = 512 - 2 * half;
        if (i >= off && i < off + half) {
            const int j = i - off;
            double ang = -6.283185307179586476925287 * (double)j / (double)(2 * half);
            g_twk[i] = make_float2((float)cos(ang), (float)sin(ang));
        }
    }
}

// bin = floor(511*sqrt(du^2+dv^2)/256), exact in double (verified: rel_err 0.0).
__global__ void tab_kernel() {
    const int pos = blockIdx.x, k = threadIdx.x;
    const int du = (int)brev9(k)   - 256;
    const int dv = (int)brev9(pos) - 256;
    const int s2 = du * du + dv * dv;
    int bin = (int)(511.0 * sqrt((double)s2) * (1.0 / 256.0));
    if (bin > 511) bin = 511;
    g_tab[pos * NS + k] = (unsigned short)bin;
}

// ---------------- FFT helpers ----------------

__device__ __forceinline__ float2 cadd(float2 a, float2 b) {
    return make_float2(a.x + b.x, a.y + b.y);
}
__device__ __forceinline__ float2 csub(float2 a, float2 b) {
    return make_float2(a.x - b.x, a.y - b.y);
}
// (u - v) * tw
__device__ __forceinline__ float2 csubmul(float2 u, float2 v, float2 tw) {
    float dr = u.x - v.x, di = u.y - v.y;
    return make_float2(dr * tw.x - di * tw.y, dr * tw.y + di * tw.x);
}

// Fused radix-8 DIF (3 radix-2 layers) on 8 points at positions p + m*h.
// T0..T3: layer-1 twiddles for m = 0..3; U0,U1: layer-2 for m mod 2; V: layer-3.
__device__ __forceinline__ void r8dif(float2 x[8],
                                      float2 T0, float2 T1, float2 T2, float2 T3,
                                      float2 U0, float2 U1, float2 V) {
    float2 a0 = cadd(x[0], x[4]), a4 = csubmul(x[0], x[4], T0);
    float2 a1 = cadd(x[1], x[5]), a5 = csubmul(x[1], x[5], T1);
    float2 a2 = cadd(x[2], x[6]), a6 = csubmul(x[2], x[6], T2);
    float2 a3 = cadd(x[3], x[7]), a7 = csubmul(x[3], x[7], T3);
    float2 b0 = cadd(a0, a2), b2 = csubmul(a0, a2, U0);
    float2 b1 = cadd(a1, a3), b3 = csubmul(a1, a3, U1);
    float2 b4 = cadd(a4, a6), b6 = csubmul(a4, a6, U0);
    float2 b5 = cadd(a5, a7), b7 = csubmul(a5, a7, U1);
    x[0] = cadd(b0, b1); x[1] = csubmul(b0, b1, V);
    x[2] = cadd(b2, b3); x[3] = csubmul(b2, b3, V);
    x[4] = cadd(b4, b5); x[5] = csubmul(b4, b5, V);
    x[6] = cadd(b6, b7); x[7] = csubmul(b6, b7, V);
}

// Final radix-8 DIF on 8 contiguous points (layers half = 4, 2, 1).
// Twiddles are constants: W_8^c and W_4^{0,1}.
__device__ __forceinline__ void r8dif_const(float2 x[8]) {
    const float r = 0.7071067811865475727f;
    float2 t0 = cadd(x[0], x[4]);
    float2 d4 = csub(x[0], x[4]);                                  // * 1
    float2 t1 = cadd(x[1], x[5]);
    float dx5 = x[1].x - x[5].x, dy5 = x[1].y - x[5].y;
    float2 d5 = make_float2(r * (dx5 + dy5), r * (dy5 - dx5));     // * (r,-r)
    float2 t2 = cadd(x[2], x[6]);
    float dx6 = x[2].x - x[6].x, dy6 = x[2].y - x[6].y;
    float2 d6 = make_float2(dy6, -dx6);                            // * (0,-1)
    float2 t3 = cadd(x[3], x[7]);
    float dx7 = x[3].x - x[7].x, dy7 = x[3].y - x[7].y;
    float2 d7 = make_float2(r * (dy7 - dx7), -r * (dx7 + dy7));    // * (-r,-r)
    // half = 2
    float2 u0 = cadd(t0, t2), u2 = csub(t0, t2);
    float2 u1 = cadd(t1, t3);
    float dxu = t1.x - t3.x, dyu = t1.y - t3.y;
    float2 u3 = make_float2(dyu, -dxu);
    float2 v0 = cadd(d4, d6), v2 = csub(d4, d6);
    float2 v1 = cadd(d5, d7);
    float dxv = d5.x - d7.x, dyv = d5.y - d7.y;
    float2 v3 = make_float2(dyv, -dxv);
    // half = 1
    x[0] = cadd(u0, u1); x[1] = csub(u0, u1);
    x[2] = cadd(u2, u3); x[3] = csub(u2, u3);
    x[4] = cadd(v0, v1); x[5] = csub(v0, v1);
    x[6] = cadd(v2, v3); x[7] = csub(v2, v3);
}

// ---------------- main kernels ----------------

// Exchange-buffer layout: idx(p) = 72*(p>>6) + 9*((p>>3)&7) + (p&7).
// Bank-conflict-free for exchange-A read, exchange-B write, and the
// contiguous pass-3 reads; exchange-A write has one 2-way pair per phase.

// One block per (4-row tile, batch). 256 threads = 4 FFT engines x 64.
// iter 0: sig 0 (target) rows 0..3; iter 1: sig 1 (error) rows 0..3.
__global__ __launch_bounds__(256) void row_fft_kernel(const float* __restrict__ z,
                                                      const float* __restrict__ tt) {
    __shared__ float2 xb[4][576];        // per-engine exchange buffer, 18.4 KB
    __shared__ float2 stage[NS][5];      // [pos][row(+pad)], 20.5 KB
    const int rt = blockIdx.x, b = blockIdx.y;
    const int t = threadIdx.x;
    const int e  = t >> 6;               // engine = row within tile
    const int tl = t & 63;
    const int s  = tl >> 3, k = tl & 7;
    const int h  = (tl >> 1) & 7;        // stage-write rotation

    // Loop-invariant twiddles (registers).
    const float2 T10 = g_twk[tl],        T11 = g_twk[64 + tl];
    const float2 T12 = g_twk[128 + tl],  T13 = g_twk[192 + tl];
    const float2 U10 = g_twk[256 + tl],  U11 = g_twk[320 + tl];
    const float2 V1  = g_twk[384 + tl];
    const float2 T20 = g_twk[448 + k],   T21 = g_twk[456 + k];
    const float2 T22 = g_twk[464 + k],   T23 = g_twk[472 + k];
    const float2 U20 = g_twk[480 + k],   U21 = g_twk[488 + k];
    const float2 V2  = g_twk[496 + k];

    const int wA = 9 * s + k;            // + 72*m
    const int wB = 72 * s + k;           // + 9*j
    const int rB = 72 * s + 9 * k;       // + c
    float2* buf = &xb[e][0];

#pragma unroll
    for (int it = 0; it < 2; it++) {
        const int row = rt * RROWS + e;
        const size_t base = ((size_t)b * NS + row) * NS;
        const float2* __restrict__ tp = (const float2*)tt + base;

        float2 x[8];
#pragma unroll
        for (int m = 0; m < 8; m++) x[m] = tp[64 * m + tl];
        if (it == 1) {
            const float2* __restrict__ zp = (const float2*)z + base;
#pragma unroll
            for (int m = 0; m < 8; m++) {
                float2 zz = zp[64 * m + tl];
                x[m] = make_float2(zz.x - x[m].x, zz.y - x[m].y);
            }
        }
        r8dif(x, T10, T11, T12, T13, U10, U11, V1);
#pragma unroll
        for (int m = 0; m < 8; m++) buf[72 * m + wA] = x[m];
        __syncthreads();                               // bar1

        float2 y[8];
#pragma unroll
        for (int j = 0; j < 8; j++) y[j] = buf[wB + 9 * j];
        r8dif(y, T20, T21, T22, T23, U20, U21, V2);
        __syncthreads();                               // bar2: drain A reads
#pragma unroll
        for (int j = 0; j < 8; j++) buf[wB + 9 * j] = y[j];
        __syncthreads();                               // bar3

        float2 zv[8];
#pragma unroll
        for (int c = 0; c < 8; c++) zv[c] = buf[rB + c];
        r8dif_const(zv);

        // Stage (conflict-free via rotation): slot [8*tl + q][e] <- zv[q].
#pragma unroll
        for (int c = 0; c < 8; c++) {
            const int q = (c + h) & 7;
            stage[8 * tl + q][e] = zv[q];
        }
        __syncthreads();                               // bar4

        // Transposed write-out: rows rt*4..rt*4+3 contiguous -> 2x STG.128.
#pragma unroll
        for (int kk = 0; kk < 2; kk++) {
            const int pos = t + kk * 256;
            float2 s0 = stage[pos][0];
            float2 s1 = stage[pos][1];
            float2 s2 = stage[pos][2];
            float2 s3 = stage[pos][3];
            float4* dst = (float4*)&g_specT[it][b][pos][rt * RROWS];
            dst[0] = make_float4(s0.x, s0.y, s1.x, s1.y);
            dst[1] = make_float4(s2.x, s2.y, s3.x, s3.y);
        }
        __syncthreads();                               // stage reads done
    }
}

// One block per (8-col tile, batch, sig). 256 threads = 4 column engines.
__global__ __launch_bounds__(256) void col_fft_kernel() {
    __shared__ float2 xb[2][4][576];     // double-buffered exchange, 36.9 KB
    __shared__ float  bins[512];
    const int tile = blockIdx.x, b = blockIdx.y, sig = blockIdx.z;
    const int t = threadIdx.x;
    const int e  = t >> 6;
    const int tl = t & 63;
    const int s  = tl >> 3, k = tl & 7;

    bins[t]       = 0.0f;
    bins[t + 256] = 0.0f;

    const float2 T10 = g_twk[tl],        T11 = g_twk[64 + tl];
    const float2 T12 = g_twk[128 + tl],  T13 = g_twk[192 + tl];
    const float2 U10 = g_twk[256 + tl],  U11 = g_twk[320 + tl];
    const float2 V1  = g_twk[384 + tl];
    const float2 T20 = g_twk[448 + k],   T21 = g_twk[456 + k];
    const float2 T22 = g_twk[464 + k],   T23 = g_twk[472 + k];
    const float2 U20 = g_twk[480 + k],   U21 = g_twk[488 + k];
    const float2 V2  = g_twk[496 + k];

    const int wA = 9 * s + k;
    const int wB = 72 * s + k;
    const int rB = 72 * s + 9 * k;

#pragma unroll
    for (int it = 0; it < 2; it++) {
        const int pos = tile * TILE_V + it * 4 + e;
        const float2* __restrict__ src = &g_specT[sig][b][pos][0];

        float2 x[8];
#pragma unroll
        for (int m = 0; m < 8; m++) x[m] = src[64 * m + tl];
        r8dif(x, T10, T11, T12, T13, U10, U11, V1);
        float2* bufA = &xb[0][e][0];
#pragma unroll
        for (int m = 0; m < 8; m++) bufA[72 * m + wA] = x[m];
        __syncthreads();                 // also covers bins init on it==0

        float2 y[8];
#pragma unroll
        for (int j = 0; j < 8; j++) y[j] = bufA[wB + 9 * j];
        r8dif(y, T20, T21, T22, T23, U20, U21, V2);
        float2* bufB = &xb[1][e][0];
#pragma unroll
        for (int j = 0; j < 8; j++) bufB[wB + 9 * j] = y[j];
        __syncthreads();

        float2 zv[8];
#pragma unroll
        for (int c = 0; c < 8; c++) zv[c] = bufB[rB + c];
        r8dif_const(zv);

        const uint4 tv = *(const uint4*)&g_tab[pos * NS + 8 * tl];
        const int b0 = tv.x & 0xffff, b1 = tv.x >> 16;
        const int b2 = tv.y & 0xffff, b3 = tv.y >> 16;
        const int b4 = tv.z & 0xffff, b5 = tv.z >> 16;
        const int b6 = tv.w & 0xffff, b7 = tv.w >> 16;
        atomicAdd(&bins[b0], zv[0].x * zv[0].x + zv[0].y * zv[0].y);
        atomicAdd(&bins[b1], zv[1].x * zv[1].x + zv[1].y * zv[1].y);
        atomicAdd(&bins[b2], zv[2].x * zv[2].x + zv[2].y * zv[2].y);
        atomicAdd(&bins[b3], zv[3].x * zv[3].x + zv[3].y * zv[3].y);
        atomicAdd(&bins[b4], zv[4].x * zv[4].x + zv[4].y * zv[4].y);
        atomicAdd(&bins[b5], zv[5].x * zv[5].x + zv[5].y * zv[5].y);
        atomicAdd(&bins[b6], zv[6].x * zv[6].x + zv[6].y * zv[6].y);
        atomicAdd(&bins[b7], zv[7].x * zv[7].x + zv[7].y * zv[7].y);
    }
    __syncthreads();

    g_part[sig][b][tile][t]       = bins[t];
    g_part[sig][b][tile][t + 256] = bins[t + 256];
}

// ---------------- reduction tree ----------------

__global__ __launch_bounds__(512) void reduce1a_kernel() {
    const int b = blockIdx.x, g = blockIdx.y, t = threadIdx.x;
    float ns = 0.0f, es = 0.0f;
#pragma unroll
    for (int tl = 0; tl < 8; tl++) {
        ns += g_part[0][b][g * 8 + tl][t];
        es += g_part[1][b][g * 8 + tl][t];
    }
    g_p2[0][b][g][t] = ns;
    g_p2[1][b][g][t] = es;
}

__global__ __launch_bounds__(512) void reduce1b_kernel() {
    __shared__ double sh[512];
    const int b = blockIdx.x, t = threadIdx.x;
    double ns = 0.0, es = 0.0;
#pragma unroll
    for (int g = 0; g < 8; g++) {
        ns += (double)g_p2[0][b][g][t];
        es += (double)g_p2[1][b][g][t];
    }
    sh[t] = (t < NBINS) ? es / fmax(ns, 1e-8) : 0.0;
    __syncthreads();
    for (int k = 256; k > 0; k >>= 1) {
        if (t < k) sh[t] += sh[t + k];
        __syncthreads();
    }
    if (t == 0) g_bsum[b] = sh[0];
}

__global__ void reduce2_kernel(float* __restrict__ out) {
    double s = 0.0;
#pragma unroll
    for (int i = 0; i < NB; i++) s += g_bsum[i];
    out[0] = (float)(s / (double)NB);
}

extern "C" void kernel_launch(void* const* d_in, const int* in_sizes, int n_in,
                              void* d_out, int out_size) {
    const float* z  = (const float*)d_in[0];   // z_ [16,512,512,2]
    const float* tt = (const float*)d_in[1];   // t_ [16,512,512,2]
    float* out = (float*)d_out;
    (void)in_sizes; (void)n_in; (void)out_size;

    twk_kernel<<<1, 512>>>();
    tab_kernel<<<NS, NS>>>();
    {
        dim3 grid(NS / RROWS, NB);
        row_fft_kernel<<<grid, 256>>>(z, tt);
    }
    {
        dim3 grid(NT, NB, 2);
        col_fft_kernel<<<grid, 256>>>();
    }
    {
        dim3 grid(NB, 8);
        reduce1a_kernel<<<grid, 512>>>();
    }
    reduce1b_kernel<<<NB, 512>>>();
    reduce2_kernel<<<1, 1>>>(out);
}

// round 9
// speedup vs baseline: 1.1185x; 1.1185x over previous
#include <cuda_runtime.h>
#include <math.h>

#define NB    16
#define NS    512
#define NBINS 511
#define TILE_V 8
#define NT    (NS / TILE_V)   // 64 column tiles
#define RROWS 4               // rows per block in row_fft

// Transposed row-FFT spectra: [sig][batch][pos][row]. 67 MB.
__device__ float2 g_specT[2][NB][NS][NS];
// Per-(sig, batch, tile) partial shell sums. 4 MB.
__device__ float  g_part[2][NB][NT][512];
// Stage-2 partials for the reduction tree.
__device__ float  g_p2[2][NB][8][512];
// Bin table [pos][k] with bit-reversal baked in. 512 KB.
__device__ unsigned short g_tab[NS * NS];
// Twiddle table, per-stage contiguous: segment for stage `half` starts at
// offset 512 - 2*half and holds W_{2*half}^j, j = 0..half-1.
__device__ float2 g_twk[512];
__device__ double g_bsum[NB];

__device__ __forceinline__ unsigned brev9(unsigned x) { return __brev(x) >> 23; }

// ---------------- setup kernels ----------------

__global__ void twk_kernel() {
    const int i = threadIdx.x;
#pragma unroll
    for (int half = 256; half >= 1; half >>= 1) {
        const int off = 512 - 2 * half;
        if (i >= off && i < off + half) {
            const int j = i - off;
            double ang = -6.283185307179586476925287 * (double)j / (double)(2 * half);
            g_twk[i] = make_float2((float)cos(ang), (float)sin(ang));
        }
    }
}

// bin = floor(511*sqrt(du^2+dv^2)/256), exact in double (verified: rel_err 0.0).
__global__ void tab_kernel() {
    const int pos = blockIdx.x, k = threadIdx.x;
    const int du = (int)brev9(k)   - 256;
    const int dv = (int)brev9(pos) - 256;
    const int s2 = du * du + dv * dv;
    int bin = (int)(511.0 * sqrt((double)s2) * (1.0 / 256.0));
    if (bin > 511) bin = 511;
    g_tab[pos * NS + k] = (unsigned short)bin;
}

// ---------------- FFT helpers ----------------

__device__ __forceinline__ float2 cadd(float2 a, float2 b) {
    return make_float2(a.x + b.x, a.y + b.y);
}
// (u - v) * tw
__device__ __forceinline__ float2 csubmul(float2 u, float2 v, float2 tw) {
    float dr = u.x - v.x, di = u.y - v.y;
    return make_float2(dr * tw.x - di * tw.y, dr * tw.y + di * tw.x);
}

// Two fused radix-2 DIF stage-layers (block sizes 4h then 2h) on one group of 4.
__device__ __forceinline__ void r4dif(float2 a, float2 b, float2 c, float2 d,
                                      float2 tw1, float2 tw1b, float2 tw2,
                                      float2& o0, float2& o1, float2& o2, float2& o3) {
    float2 t0 = cadd(a, c);
    float2 t1 = csubmul(a, c, tw1);
    float2 t2 = cadd(b, d);
    float2 t3 = csubmul(b, d, tw1b);
    o0 = cadd(t0, t2);
    o1 = csubmul(t0, t2, tw2);
    o2 = cadd(t1, t3);
    o3 = csubmul(t1, t3, tw2);
}

// Generic shuffle butterfly for half = 16, 8, 4.
__device__ __forceinline__ float2 bfly_shfl(float2 x, int half, float2 tw, int L) {
    float px = __shfl_xor_sync(0xffffffffu, x.x, half);
    float py = __shfl_xor_sync(0xffffffffu, x.y, half);
    if ((L & half) == 0)
        return make_float2(x.x + px, x.y + py);
    float dr = px - x.x, di = py - x.y;
    return make_float2(dr * tw.x - di * tw.y, dr * tw.y + di * tw.x);
}

// half = 2: twiddle is W_4^{L&1} = (1,0) or (0,-1) -> swap/negate.
__device__ __forceinline__ float2 bfly_h2(float2 x, int L) {
    float px = __shfl_xor_sync(0xffffffffu, x.x, 2);
    float py = __shfl_xor_sync(0xffffffffu, x.y, 2);
    if ((L & 2) == 0) return make_float2(x.x + px, x.y + py);
    float dr = px - x.x, di = py - x.y;
    return (L & 1) ? make_float2(di, -dr) : make_float2(dr, di);
}

// half = 1: plain add/sub.
__device__ __forceinline__ float2 bfly_h1(float2 x, int L) {
    float px = __shfl_xor_sync(0xffffffffu, x.x, 1);
    float py = __shfl_xor_sync(0xffffffffu, x.y, 1);
    if ((L & 1) == 0) return make_float2(x.x + px, x.y + py);
    return make_float2(px - x.x, py - x.y);
}

// Last 5 stages (half 16..1) for 4 register-resident points at positions
// pb, pb+32, pb+64, pb+96.
__device__ __forceinline__ void fft_reg_stages4(float2& x0, float2& x1,
                                                float2& x2, float2& x3,
                                                float2 tw16, float2 tw8, float2 tw4,
                                                int L) {
    x0 = bfly_shfl(x0, 16, tw16, L); x1 = bfly_shfl(x1, 16, tw16, L);
    x2 = bfly_shfl(x2, 16, tw16, L); x3 = bfly_shfl(x3, 16, tw16, L);
    x0 = bfly_shfl(x0, 8, tw8, L);   x1 = bfly_shfl(x1, 8, tw8, L);
    x2 = bfly_shfl(x2, 8, tw8, L);   x3 = bfly_shfl(x3, 8, tw8, L);
    x0 = bfly_shfl(x0, 4, tw4, L);   x1 = bfly_shfl(x1, 4, tw4, L);
    x2 = bfly_shfl(x2, 4, tw4, L);   x3 = bfly_shfl(x3, 4, tw4, L);
    x0 = bfly_h2(x0, L); x1 = bfly_h2(x1, L);
    x2 = bfly_h2(x2, L); x3 = bfly_h2(x3, L);
    x0 = bfly_h1(x0, L); x1 = bfly_h1(x1, L);
    x2 = bfly_h1(x2, L); x3 = bfly_h1(x3, L);
}

// ---------------- main kernels ----------------

// One block per (4-row tile, batch). 256 threads = 2 signal engines x 128.
// Single exchange buffer (8 KB) + 32 KB transpose stage. Inputs read with
// __ldcs (evict-first) so g_specT stays L2-resident for the col pass.
__global__ __launch_bounds__(256, 5) void row_fft_kernel(const float* __restrict__ z,
                                                         const float* __restrict__ tt) {
    __shared__ float2 w[2][NS];             // [engine][pos]   8 KB
    __shared__ float2 stage[2][RROWS][NS];  // [sig][row][pos] 32 KB
    __shared__ float2 s_tw[512];            // 4 KB
    const int rt = blockIdx.x, b = blockIdx.y;
    const int t = threadIdx.x;
    const int f = t >> 7;          // signal: 0 = target, 1 = error
    const int g = t & 127;
    const int L = t & 31;
    const int ww = g >> 5;
    const int pb = 128 * ww + L;

    s_tw[t]       = g_twk[t];
    s_tw[t + 256] = g_twk[t + 256];
    __syncthreads();

#pragma unroll
    for (int r = 0; r < RROWS; r++) {
        const int row = rt * RROWS + r;
        const size_t base = ((size_t)b * NS + row) * NS;
        const float2* __restrict__ tp = (const float2*)tt + base;

        float2 a0 = __ldcs(&tp[g]),       a1 = __ldcs(&tp[g + 128]);
        float2 a2 = __ldcs(&tp[g + 256]), a3 = __ldcs(&tp[g + 384]);
        if (f == 1) {
            const float2* __restrict__ zp = (const float2*)z + base;
            float2 z0 = __ldcs(&zp[g]),       z1 = __ldcs(&zp[g + 128]);
            float2 z2 = __ldcs(&zp[g + 256]), z3 = __ldcs(&zp[g + 384]);
            a0 = make_float2(z0.x - a0.x, z0.y - a0.y);
            a1 = make_float2(z1.x - a1.x, z1.y - a1.y);
            a2 = make_float2(z2.x - a2.x, z2.y - a2.y);
            a3 = make_float2(z3.x - a3.x, z3.y - a3.y);
        }

        float2 o0, o1, o2, o3;
        r4dif(a0, a1, a2, a3, s_tw[g], s_tw[g + 128], s_tw[256 + g], o0, o1, o2, o3);
        float2* wf = w[f];
        wf[g] = o0; wf[g + 128] = o1; wf[g + 256] = o2; wf[g + 384] = o3;
        __syncthreads();

        float2 b0 = wf[pb], b1 = wf[pb + 32], b2 = wf[pb + 64], b3 = wf[pb + 96];
        float2 x0, x1, x2, x3;
        r4dif(b0, b1, b2, b3, s_tw[384 + L], s_tw[416 + L], s_tw[448 + L],
              x0, x1, x2, x3);
        fft_reg_stages4(x0, x1, x2, x3,
                        s_tw[480 + (L & 15)], s_tw[496 + (L & 7)], s_tw[504 + (L & 3)],
                        L);

        stage[f][r][pb]      = x0;
        stage[f][r][pb + 32] = x1;
        stage[f][r][pb + 64] = x2;
        stage[f][r][pb + 96] = x3;
        __syncthreads();               // w reuse next r; also finalizes stage on last r
    }

    // Transposed write-out: rows rt*4..rt*4+3 contiguous -> 2x STG.128 per item.
#pragma unroll
    for (int k = 0; k < 4; k++) {
        const int i   = t + k * 256;     // 0..1023
        const int fo  = i >> 9;
        const int pos = i & 511;
        float2 s0 = stage[fo][0][pos];
        float2 s1 = stage[fo][1][pos];
        float2 s2 = stage[fo][2][pos];
        float2 s3 = stage[fo][3][pos];
        float4* dst = (float4*)&g_specT[fo][b][pos][rt * RROWS];
        dst[0] = make_float4(s0.x, s0.y, s1.x, s1.y);
        dst[1] = make_float4(s2.x, s2.y, s3.x, s3.y);
    }
}

// One block per (8-col tile, batch, sig). 256 threads = 2 column engines.
// Twiddles fetched from s_tw inside the loop (register relief); reg cap for
// 6 blocks/SM residency.
__global__ __launch_bounds__(256, 6) void col_fft_kernel() {
    __shared__ float2 w[2][2 * NS]; // [parity][engine*512 + pos]  16 KB
    __shared__ float2 s_tw[512];    // 4 KB
    __shared__ float  bins[512];    // 2 KB
    const int tile = blockIdx.x, b = blockIdx.y, sig = blockIdx.z;
    const int t = threadIdx.x;
    const int f = t >> 7;
    const int g = t & 127;
    const int L = t & 31;
    const int ww = g >> 5;
    const int pb = 128 * ww + L;

    s_tw[t]       = g_twk[t];
    s_tw[t + 256] = g_twk[t + 256];
    bins[t]       = 0.0f;
    bins[t + 256] = 0.0f;
    __syncthreads();

#pragma unroll
    for (int c = 0; c < TILE_V; c += 2) {
        const int pos = tile * TILE_V + c + f;
        const float2* __restrict__ src = &g_specT[sig][b][pos][0];

        float2 a0 = src[g], a1 = src[g + 128], a2 = src[g + 256], a3 = src[g + 384];
        float2 o0, o1, o2, o3;
        r4dif(a0, a1, a2, a3, s_tw[g], s_tw[g + 128], s_tw[256 + g], o0, o1, o2, o3);

        float2* wf = &w[(c >> 1) & 1][f * NS];
        wf[g] = o0; wf[g + 128] = o1; wf[g + 256] = o2; wf[g + 384] = o3;
        __syncthreads();

        float2 b0 = wf[pb], b1 = wf[pb + 32], b2 = wf[pb + 64], b3 = wf[pb + 96];
        float2 x0, x1, x2, x3;
        r4dif(b0, b1, b2, b3, s_tw[384 + L], s_tw[416 + L], s_tw[448 + L],
              x0, x1, x2, x3);
        fft_reg_stages4(x0, x1, x2, x3,
                        s_tw[480 + (L & 15)], s_tw[496 + (L & 7)], s_tw[504 + (L & 3)],
                        L);

        const unsigned short* __restrict__ tb = &g_tab[pos * NS];
        atomicAdd(&bins[tb[pb]],      x0.x * x0.x + x0.y * x0.y);
        atomicAdd(&bins[tb[pb + 32]], x1.x * x1.x + x1.y * x1.y);
        atomicAdd(&bins[tb[pb + 64]], x2.x * x2.x + x2.y * x2.y);
        atomicAdd(&bins[tb[pb + 96]], x3.x * x3.x + x3.y * x3.y);
    }
    __syncthreads();

    g_part[sig][b][tile][t]       = bins[t];
    g_part[sig][b][tile][t + 256] = bins[t + 256];
}

// ---------------- reduction tree ----------------

__global__ __launch_bounds__(512) void reduce1a_kernel() {
    const int b = blockIdx.x, g = blockIdx.y, t = threadIdx.x;
    float ns = 0.0f, es = 0.0f;
#pragma unroll
    for (int tl = 0; tl < 8; tl++) {
        ns += g_part[0][b][g * 8 + tl][t];
        es += g_part[1][b][g * 8 + tl][t];
    }
    g_p2[0][b][g][t] = ns;
    g_p2[1][b][g][t] = es;
}

__global__ __launch_bounds__(512) void reduce1b_kernel() {
    __shared__ double sh[512];
    const int b = blockIdx.x, t = threadIdx.x;
    double ns = 0.0, es = 0.0;
#pragma unroll
    for (int g = 0; g < 8; g++) {
        ns += (double)g_p2[0][b][g][t];
        es += (double)g_p2[1][b][g][t];
    }
    sh[t] = (t < NBINS) ? es / fmax(ns, 1e-8) : 0.0;
    __syncthreads();
    for (int k = 256; k > 0; k >>= 1) {
        if (t < k) sh[t] += sh[t + k];
        __syncthreads();
    }
    if (t == 0) g_bsum[b] = sh[0];
}

__global__ void reduce2_kernel(float* __restrict__ out) {
    double s = 0.0;
#pragma unroll
    for (int i = 0; i < NB; i++) s += g_bsum[i];
    out[0] = (float)(s / (double)NB);
}

extern "C" void kernel_launch(void* const* d_in, const int* in_sizes, int n_in,
                              void* d_out, int out_size) {
    const float* z  = (const float*)d_in[0];   // z_ [16,512,512,2]
    const float* tt = (const float*)d_in[1];   // t_ [16,512,512,2]
    float* out = (float*)d_out;
    (void)in_sizes; (void)n_in; (void)out_size;

    twk_kernel<<<1, 512>>>();
    tab_kernel<<<NS, NS>>>();
    {
        dim3 grid(NS / RROWS, NB);
        row_fft_kernel<<<grid, 256>>>(z, tt);
    }
    {
        dim3 grid(NT, NB, 2);
        col_fft_kernel<<<grid, 256>>>();
    }
    {
        dim3 grid(NB, 8);
        reduce1a_kernel<<<grid, 512>>>();
    }
    reduce1b_kernel<<<NB, 512>>>();
    reduce2_kernel<<<1, 1>>>(out);
}